// round 14
// baseline (speedup 1.0000x reference)
#include <cuda_runtime.h>
#include <stdint.h>

#define DIM_IN 16
#define CH 128
#define DIM_OUT 99
#define MAX_NNZ 512
#define MAX_PADDED 1024
#define NGROUPS ((DIM_OUT + 3) / 4)   // 25 groups of 4 rows
#define EPB 2
#define THREADS (EPB * 64)

// 16-byte term (ulonglong2): .x = ox | (oy<<16) in low 32 (u16 byte offsets
// into the 8 KB row block), .y = {cg, cg} pre-packed for f32x2 FMA.
// group (uint4): .x = kG | (n<<16)
//                .y = offA | (offB<<16)   (output byte offsets, row*512)
//                .z = offC | (offD<<16)
struct __align__(16) CMeta {
    ulonglong2 terms[MAX_PADDED];
    uint4      groups[NGROUPS];
};
__device__    CMeta g_meta;
__constant__  CMeta c_meta;

// ---------------------------------------------------------------------------
// Prep: fully parallel (no serial thread-0 prefix chains). Stable CSR sort by
// mu3 via rank-scatter, rows ordered by count desc (parallel rank), groups of
// 4 rows zero-padded to group max. Deterministic.
// ---------------------------------------------------------------------------
__global__ void prep_kernel(const int* __restrict__ mu1,
                            const int* __restrict__ mu2,
                            const int* __restrict__ mu3,
                            const float* __restrict__ cg,
                            int nnz)
{
    __shared__ int   sm3[MAX_NNZ];
    __shared__ uint2 st8[MAX_NNZ];       // CSR-sorted compact terms
    __shared__ int   start[DIM_OUT + 1];
    __shared__ int   cnt[DIM_OUT];
    __shared__ int   order[DIM_OUT];
    __shared__ int   gk[NGROUPS], gn[NGROUPS];
    int t = threadIdx.x;

    if (t < DIM_OUT) cnt[t] = 0;
    __syncthreads();

    for (int k = t; k < nnz; k += blockDim.x) {
        int m = mu3[k];
        sm3[k] = m;
        atomicAdd(&cnt[m], 1);
    }
    __syncthreads();

    // parallel start prefix (independent pipelined LDS per thread)
    if (t <= DIM_OUT) {
        int s = 0;
        for (int r = 0; r < t; r++) s += cnt[r];
        start[t] = s;
    }
    // parallel rank: rows ordered by (count desc, row id asc)
    if (t < DIM_OUT) {
        int c = cnt[t];
        int rk = 0;
        for (int r = 0; r < DIM_OUT; r++) {
            int cr = cnt[r];
            rk += (cr > c) || (cr == c && r < t);
        }
        order[rk] = t;
    }
    __syncthreads();

    // stable scatter into CSR (rank = #earlier terms with same mu3)
    for (int k = t; k < nnz; k += blockDim.x) {
        int m = sm3[k];
        int rank = 0;
        for (int j = 0; j < k; j++) rank += (sm3[j] == m);
        unsigned int ox = (unsigned int)mu1[k] * (CH * 4u);
        unsigned int oy = (unsigned int)mu2[k] * (CH * 4u);
        uint2 tm;
        tm.x = ox | (oy << 16);
        tm.y = __float_as_uint(cg[k]);
        st8[start[m] + rank] = tm;
    }
    // parallel group build (counts sorted desc => group's first row = max)
    if (t < NGROUPS) {
        int i0 = 4 * t;
        int n  = cnt[order[i0]];
        int base = 0;
        for (int g2 = 0; g2 < t; g2++) base += cnt[order[4 * g2]];
        base *= 4;
        gk[t] = base;
        gn[t] = n;
        int rA = order[i0];
        int rB = order[(i0 + 1 < DIM_OUT) ? i0 + 1 : DIM_OUT - 1];
        int rC = order[(i0 + 2 < DIM_OUT) ? i0 + 2 : DIM_OUT - 1];
        int rD = order[(i0 + 3 < DIM_OUT) ? i0 + 3 : DIM_OUT - 1];
        uint4 gd;
        gd.x = (unsigned int)base | ((unsigned int)n << 16);
        gd.y = (unsigned int)(rA * CH * 4) | ((unsigned int)(rB * CH * 4) << 16);
        gd.z = (unsigned int)(rC * CH * 4) | ((unsigned int)(rD * CH * 4) << 16);
        gd.w = 0u;
        g_meta.groups[t] = gd;
    }
    __syncthreads();

    // parallel emit of padded 16-byte term streams (one thread per row slot)
    for (int i = t; i < 4 * NGROUPS; i += blockDim.x) {
        int g = i >> 2;
        int s = i & 3;
        int oi = (i < DIM_OUT) ? i : DIM_OUT - 1;
        int row = order[oi];
        int n   = gn[g];
        int kS  = gk[g] + s * n;
        int sR = start[row], cR = cnt[row];
        for (int j = 0; j < n; j++) {
            ulonglong2 e;
            if (j < cR) {
                uint2 tm = st8[sR + j];
                e.x = (unsigned long long)tm.x;
                e.y = ((unsigned long long)tm.y << 32) | (unsigned long long)tm.y;
            } else {
                e.x = 0ull;
                e.y = 0ull;      // cg = {+0,+0}: exact no-op FMA
            }
            g_meta.terms[kS + j] = e;
        }
    }
}

// ---------------------------------------------------------------------------
// Main: 2 edges per 128-thread block; 64 threads/edge, one channel pair per
// thread, packed f32x2. FOUR output rows as interleaved independent streams
// per group. Terms from constant memory (LDC.128 broadcast, cg
// pre-duplicated); store offsets premultiplied in the group descriptor.
// Each real output element written once; duplicated tail rows rewrite
// identical values.
// ---------------------------------------------------------------------------
__global__ __launch_bounds__(THREADS, 6)
void tp_kernel(const float* __restrict__ x,
               const float* __restrict__ y,
               float* __restrict__ out)
{
    __shared__ __align__(16) float sx[EPB * DIM_IN * CH];   // 16 KB
    __shared__ __align__(16) float sy[EPB * DIM_IN * CH];   // 16 KB

    const int t    = threadIdx.x;
    const int sub  = t >> 6;
    const int lane = t & 63;
    const long long ebase = (long long)blockIdx.x * EPB;

    const float4* x4 = (const float4*)(x + ebase * (DIM_IN * CH));
    const float4* y4 = (const float4*)(y + ebase * (DIM_IN * CH));
#pragma unroll
    for (int i = 0; i < (EPB * DIM_IN * CH / 4) / THREADS; i++) {
        ((float4*)sx)[t + i * THREADS] = x4[t + i * THREADS];
        ((float4*)sy)[t + i * THREADS] = y4[t + i * THREADS];
    }
    __syncthreads();

    const char* sxb = (const char*)(sx + sub * (DIM_IN * CH)) + lane * 8;
    const char* syb = (const char*)(sy + sub * (DIM_IN * CH)) + lane * 8;
    char* outb = (char*)(out + (ebase + sub) * (DIM_OUT * CH) + lane * 2);

#pragma unroll 1
    for (int g = 0; g < NGROUPS; g++) {
        uint4 gd = c_meta.groups[g];
        const int kG = gd.x & 0xFFFFu;
        const int n  = gd.x >> 16;

        const ulonglong2* tA = c_meta.terms + kG;
        const ulonglong2* tB = tA + n;
        const ulonglong2* tC = tB + n;
        const ulonglong2* tD = tC + n;

        unsigned long long accA = 0ull, accB = 0ull;
        unsigned long long accC = 0ull, accD = 0ull;
#pragma unroll 4
        for (int j = 0; j < n; j++) {
            ulonglong2 ta = tA[j];
            ulonglong2 tb = tB[j];
            ulonglong2 tc = tC[j];
            ulonglong2 td = tD[j];
            unsigned int ma = (unsigned int)ta.x;
            unsigned int mb = (unsigned int)tb.x;
            unsigned int mc = (unsigned int)tc.x;
            unsigned int md = (unsigned int)td.x;
            unsigned long long xvA = *(const unsigned long long*)(sxb + (ma & 0xFFFFu));
            unsigned long long yvA = *(const unsigned long long*)(syb + (ma >> 16));
            unsigned long long xvB = *(const unsigned long long*)(sxb + (mb & 0xFFFFu));
            unsigned long long yvB = *(const unsigned long long*)(syb + (mb >> 16));
            unsigned long long xvC = *(const unsigned long long*)(sxb + (mc & 0xFFFFu));
            unsigned long long yvC = *(const unsigned long long*)(syb + (mc >> 16));
            unsigned long long xvD = *(const unsigned long long*)(sxb + (md & 0xFFFFu));
            unsigned long long yvD = *(const unsigned long long*)(syb + (md >> 16));
            unsigned long long pA, pB, pC, pD;
            asm("mul.rn.f32x2 %0, %1, %2;" : "=l"(pA) : "l"(xvA), "l"(yvA));
            asm("mul.rn.f32x2 %0, %1, %2;" : "=l"(pB) : "l"(xvB), "l"(yvB));
            asm("mul.rn.f32x2 %0, %1, %2;" : "=l"(pC) : "l"(xvC), "l"(yvC));
            asm("mul.rn.f32x2 %0, %1, %2;" : "=l"(pD) : "l"(xvD), "l"(yvD));
            asm("fma.rn.f32x2 %0, %1, %2, %3;"
                : "=l"(accA) : "l"(pA), "l"(ta.y), "l"(accA));
            asm("fma.rn.f32x2 %0, %1, %2, %3;"
                : "=l"(accB) : "l"(pB), "l"(tb.y), "l"(accB));
            asm("fma.rn.f32x2 %0, %1, %2, %3;"
                : "=l"(accC) : "l"(pC), "l"(tc.y), "l"(accC));
            asm("fma.rn.f32x2 %0, %1, %2, %3;"
                : "=l"(accD) : "l"(pD), "l"(td.y), "l"(accD));
        }
        *(unsigned long long*)(outb + (gd.y & 0xFFFFu)) = accA;
        *(unsigned long long*)(outb + (gd.y >> 16))     = accB;
        *(unsigned long long*)(outb + (gd.z & 0xFFFFu)) = accC;
        *(unsigned long long*)(outb + (gd.z >> 16))     = accD;
    }
}

// ---------------------------------------------------------------------------
// Inputs (metadata order): x f32 [N,16,128], y f32 [N,16,128],
//                          mu1 i32 [nnz], mu2 i32 [nnz], mu3 i32 [nnz], cg f32 [nnz]
// Output: f32 [N,99,128]
// ---------------------------------------------------------------------------
extern "C" void kernel_launch(void* const* d_in, const int* in_sizes, int n_in,
                              void* d_out, int out_size)
{
    const float* x   = (const float*)d_in[0];
    const float* y   = (const float*)d_in[1];
    const int*   mu1 = (const int*)d_in[2];
    const int*   mu2 = (const int*)d_in[3];
    const int*   mu3 = (const int*)d_in[4];
    const float* cg  = (const float*)d_in[5];

    int nnz = in_sizes[2];
    if (nnz > MAX_NNZ) nnz = MAX_NNZ;   // capacity guard (actual nnz ~350)
    int N = in_sizes[0] / (DIM_IN * CH);
    int nBlocks = (N + EPB - 1) / EPB;

    prep_kernel<<<1, 1024>>>(mu1, mu2, mu3, cg, nnz);

    // single D2D copy of all prepared metadata into constant memory
    void* gm_addr = nullptr;
    cudaGetSymbolAddress(&gm_addr, g_meta);
    cudaMemcpyToSymbolAsync(c_meta, gm_addr, sizeof(CMeta), 0,
                            cudaMemcpyDeviceToDevice, 0);

    tp_kernel<<<nBlocks, THREADS>>>(x, y, (float*)d_out);
}

// round 15
// speedup vs baseline: 1.1043x; 1.1043x over previous
#include <cuda_runtime.h>
#include <stdint.h>

#define DIM_IN 16
#define CH 128
#define DIM_OUT 99
#define MAX_NNZ 512
#define MAX_PADDED 1024
#define NGROUPS ((DIM_OUT + 3) / 4)   // 25 groups of 4 rows
#define EPB 2
#define THREADS (EPB * 64)

// 16-byte term (ulonglong2): .x = ox | (oy<<16) in low 32 (u16 byte offsets
// into the 8 KB row block), .y = {cg, cg} pre-packed for f32x2 FMA.
// group (uint2): .x = kG | (n<<16) | (rowA<<24) ; .y = rowB|(rowC<<8)|(rowD<<16)
struct __align__(16) CMeta {
    ulonglong2 terms[MAX_PADDED];
    uint2      groups[NGROUPS];
};
__device__    CMeta g_meta;
__constant__  CMeta c_meta;

// ---------------------------------------------------------------------------
// Prep: fully parallel (no serial thread-0 chains). Stable CSR sort by mu3
// via rank-scatter, rows ordered by count desc (parallel rank), groups of 4
// rows zero-padded to group max. Deterministic.
// ---------------------------------------------------------------------------
__global__ void prep_kernel(const int* __restrict__ mu1,
                            const int* __restrict__ mu2,
                            const int* __restrict__ mu3,
                            const float* __restrict__ cg,
                            int nnz)
{
    __shared__ int   sm3[MAX_NNZ];
    __shared__ uint2 st8[MAX_NNZ];       // CSR-sorted compact terms
    __shared__ int   start[DIM_OUT + 1];
    __shared__ int   cnt[DIM_OUT];
    __shared__ int   order[DIM_OUT];
    __shared__ int   gk[NGROUPS], gn[NGROUPS];
    int t = threadIdx.x;

    if (t < DIM_OUT) cnt[t] = 0;
    __syncthreads();

    for (int k = t; k < nnz; k += blockDim.x) {
        int m = mu3[k];
        sm3[k] = m;
        atomicAdd(&cnt[m], 1);
    }
    __syncthreads();

    // parallel start prefix (independent pipelined LDS per thread)
    if (t <= DIM_OUT) {
        int s = 0;
        for (int r = 0; r < t; r++) s += cnt[r];
        start[t] = s;
    }
    // parallel rank: rows ordered by (count desc, row id asc)
    if (t < DIM_OUT) {
        int c = cnt[t];
        int rk = 0;
        for (int r = 0; r < DIM_OUT; r++) {
            int cr = cnt[r];
            rk += (cr > c) || (cr == c && r < t);
        }
        order[rk] = t;
    }
    __syncthreads();

    // stable scatter into CSR (rank = #earlier terms with same mu3);
    // rank loop is independent pipelined LDS+compare per j.
    for (int k = t; k < nnz; k += blockDim.x) {
        int m = sm3[k];
        int rank = 0;
        for (int j = 0; j < k; j++) rank += (sm3[j] == m);
        unsigned int ox = (unsigned int)mu1[k] * (CH * 4u);
        unsigned int oy = (unsigned int)mu2[k] * (CH * 4u);
        uint2 tm;
        tm.x = ox | (oy << 16);
        tm.y = __float_as_uint(cg[k]);
        st8[start[m] + rank] = tm;
    }
    // parallel group build (counts sorted desc => group's first row = max)
    if (t < NGROUPS) {
        int i0 = 4 * t;
        int n  = cnt[order[i0]];
        int base = 0;
        for (int g2 = 0; g2 < t; g2++) base += cnt[order[4 * g2]];
        base *= 4;
        gk[t] = base;
        gn[t] = n;
        int rA = order[i0];
        int rB = order[(i0 + 1 < DIM_OUT) ? i0 + 1 : DIM_OUT - 1];
        int rC = order[(i0 + 2 < DIM_OUT) ? i0 + 2 : DIM_OUT - 1];
        int rD = order[(i0 + 3 < DIM_OUT) ? i0 + 3 : DIM_OUT - 1];
        uint2 gd;
        gd.x = (unsigned int)base | ((unsigned int)n << 16)
             | ((unsigned int)rA << 24);
        gd.y = (unsigned int)rB | ((unsigned int)rC << 8)
             | ((unsigned int)rD << 16);
        g_meta.groups[t] = gd;
    }
    __syncthreads();

    // parallel emit of padded 16-byte term streams (one thread per row slot)
    for (int i = t; i < 4 * NGROUPS; i += blockDim.x) {
        int g = i >> 2;
        int s = i & 3;
        int oi = (i < DIM_OUT) ? i : DIM_OUT - 1;
        int row = order[oi];
        int n   = gn[g];
        int kS  = gk[g] + s * n;
        int sR = start[row], cR = cnt[row];
        for (int j = 0; j < n; j++) {
            ulonglong2 e;
            if (j < cR) {
                uint2 tm = st8[sR + j];
                e.x = (unsigned long long)tm.x;
                e.y = ((unsigned long long)tm.y << 32) | (unsigned long long)tm.y;
            } else {
                e.x = 0ull;
                e.y = 0ull;      // cg = {+0,+0}: exact no-op FMA
            }
            g_meta.terms[kS + j] = e;
        }
    }
}

// ---------------------------------------------------------------------------
// Main (exact R12 structure — measured 66.2us): 2 edges per 128-thread block;
// 64 threads/edge, one channel pair per thread, packed f32x2. FOUR output
// rows as interleaved independent streams per group, unroll x4. Terms from
// constant memory (LDC.128 broadcast, cg pre-duplicated). Each real output
// element written once; duplicated tail rows rewrite identical values.
// ---------------------------------------------------------------------------
__global__ __launch_bounds__(THREADS, 5)
void tp_kernel(const float* __restrict__ x,
               const float* __restrict__ y,
               float* __restrict__ out)
{
    __shared__ __align__(16) float sx[EPB * DIM_IN * CH];   // 16 KB
    __shared__ __align__(16) float sy[EPB * DIM_IN * CH];   // 16 KB

    const int t    = threadIdx.x;
    const int sub  = t >> 6;
    const int lane = t & 63;
    const long long ebase = (long long)blockIdx.x * EPB;

    const float4* x4 = (const float4*)(x + ebase * (DIM_IN * CH));
    const float4* y4 = (const float4*)(y + ebase * (DIM_IN * CH));
#pragma unroll
    for (int i = 0; i < (EPB * DIM_IN * CH / 4) / THREADS; i++) {
        ((float4*)sx)[t + i * THREADS] = x4[t + i * THREADS];
        ((float4*)sy)[t + i * THREADS] = y4[t + i * THREADS];
    }
    __syncthreads();

    const char* sxb = (const char*)(sx + sub * (DIM_IN * CH)) + lane * 8;
    const char* syb = (const char*)(sy + sub * (DIM_IN * CH)) + lane * 8;
    float* outb = out + (ebase + sub) * (DIM_OUT * CH) + lane * 2;

#pragma unroll 1
    for (int g = 0; g < NGROUPS; g++) {
        uint2 gd = c_meta.groups[g];
        const int kG = gd.x & 0xFFFFu;
        const int n  = (gd.x >> 16) & 0xFFu;
        const int oA = gd.x >> 24;
        const int oB = gd.y & 0xFFu;
        const int oC = (gd.y >> 8) & 0xFFu;
        const int oD = (gd.y >> 16) & 0xFFu;

        const ulonglong2* tA = c_meta.terms + kG;
        const ulonglong2* tB = tA + n;
        const ulonglong2* tC = tB + n;
        const ulonglong2* tD = tC + n;

        unsigned long long accA = 0ull, accB = 0ull;
        unsigned long long accC = 0ull, accD = 0ull;
#pragma unroll 4
        for (int j = 0; j < n; j++) {
            ulonglong2 ta = tA[j];
            ulonglong2 tb = tB[j];
            ulonglong2 tc = tC[j];
            ulonglong2 td = tD[j];
            unsigned int ma = (unsigned int)ta.x;
            unsigned int mb = (unsigned int)tb.x;
            unsigned int mc = (unsigned int)tc.x;
            unsigned int md = (unsigned int)td.x;
            unsigned long long xvA = *(const unsigned long long*)(sxb + (ma & 0xFFFFu));
            unsigned long long yvA = *(const unsigned long long*)(syb + (ma >> 16));
            unsigned long long xvB = *(const unsigned long long*)(sxb + (mb & 0xFFFFu));
            unsigned long long yvB = *(const unsigned long long*)(syb + (mb >> 16));
            unsigned long long xvC = *(const unsigned long long*)(sxb + (mc & 0xFFFFu));
            unsigned long long yvC = *(const unsigned long long*)(syb + (mc >> 16));
            unsigned long long xvD = *(const unsigned long long*)(sxb + (md & 0xFFFFu));
            unsigned long long yvD = *(const unsigned long long*)(syb + (md >> 16));
            unsigned long long pA, pB, pC, pD;
            asm("mul.rn.f32x2 %0, %1, %2;" : "=l"(pA) : "l"(xvA), "l"(yvA));
            asm("mul.rn.f32x2 %0, %1, %2;" : "=l"(pB) : "l"(xvB), "l"(yvB));
            asm("mul.rn.f32x2 %0, %1, %2;" : "=l"(pC) : "l"(xvC), "l"(yvC));
            asm("mul.rn.f32x2 %0, %1, %2;" : "=l"(pD) : "l"(xvD), "l"(yvD));
            asm("fma.rn.f32x2 %0, %1, %2, %3;"
                : "=l"(accA) : "l"(pA), "l"(ta.y), "l"(accA));
            asm("fma.rn.f32x2 %0, %1, %2, %3;"
                : "=l"(accB) : "l"(pB), "l"(tb.y), "l"(accB));
            asm("fma.rn.f32x2 %0, %1, %2, %3;"
                : "=l"(accC) : "l"(pC), "l"(tc.y), "l"(accC));
            asm("fma.rn.f32x2 %0, %1, %2, %3;"
                : "=l"(accD) : "l"(pD), "l"(td.y), "l"(accD));
        }
        *(unsigned long long*)(outb + oA * CH) = accA;
        *(unsigned long long*)(outb + oB * CH) = accB;
        *(unsigned long long*)(outb + oC * CH) = accC;
        *(unsigned long long*)(outb + oD * CH) = accD;
    }
}

// ---------------------------------------------------------------------------
// Inputs (metadata order): x f32 [N,16,128], y f32 [N,16,128],
//                          mu1 i32 [nnz], mu2 i32 [nnz], mu3 i32 [nnz], cg f32 [nnz]
// Output: f32 [N,99,128]
// ---------------------------------------------------------------------------
extern "C" void kernel_launch(void* const* d_in, const int* in_sizes, int n_in,
                              void* d_out, int out_size)
{
    const float* x   = (const float*)d_in[0];
    const float* y   = (const float*)d_in[1];
    const int*   mu1 = (const int*)d_in[2];
    const int*   mu2 = (const int*)d_in[3];
    const int*   mu3 = (const int*)d_in[4];
    const float* cg  = (const float*)d_in[5];

    int nnz = in_sizes[2];
    if (nnz > MAX_NNZ) nnz = MAX_NNZ;   // capacity guard (actual nnz ~350)
    int N = in_sizes[0] / (DIM_IN * CH);
    int nBlocks = (N + EPB - 1) / EPB;

    prep_kernel<<<1, 1024>>>(mu1, mu2, mu3, cg, nnz);

    // single D2D copy of all prepared metadata into constant memory
    void* gm_addr = nullptr;
    cudaGetSymbolAddress(&gm_addr, g_meta);
    cudaMemcpyToSymbolAsync(c_meta, gm_addr, sizeof(CMeta), 0,
                            cudaMemcpyDeviceToDevice, 0);

    tp_kernel<<<nBlocks, THREADS>>>(x, y, (float*)d_out);
}